// round 1
// baseline (speedup 1.0000x reference)
#include <cuda_runtime.h>
#include <math.h>

// Sinkhorn distance, N=M=4096, D=256, EPS=0.1, 100 iterations.
// All dual potentials and the cost matrix are kept pre-scaled by LOG2E/EPS so
// the inner loops use exp2/log2 directly (MUFU.EX2 / MUFU.LG2).

#define NN 4096
#define KK 256
#define SCALEF 14.4269504088896340736f   // log2(e)/EPS
#define NEG_BIG (-1e30f)

// ---- device scratch (no allocations allowed) ----
__device__ float g_C2[(size_t)NN * NN];   // 64 MB: C * SCALEF
__device__ float g_u[NN];                 // u * SCALEF (i.e. u/(eps) * log2e)
__device__ float g_v[NN];
__device__ float g_xs[NN];                // |x_i|^2
__device__ float g_ys[NN];                // |y_j|^2
__device__ float g_part[NN];              // per-row partials of final cost

__device__ __forceinline__ float ex2f(float x) {
    float r; asm("ex2.approx.ftz.f32 %0, %1;" : "=f"(r) : "f"(x)); return r;
}
__device__ __forceinline__ float lg2f(float x) {
    float r; asm("lg2.approx.ftz.f32 %0, %1;" : "=f"(r) : "f"(x)); return r;
}

// ---------------------------------------------------------------------------
// squared row norms of x and y. global warp w handles one row.
// grid: 1024 blocks x 256 threads -> 8192 warps = 2*4096 rows
__global__ __launch_bounds__(256) void sqnorm_kernel(const float* __restrict__ X,
                                                     const float* __restrict__ Y) {
    int gw = (blockIdx.x * 256 + threadIdx.x) >> 5;
    int lane = threadIdx.x & 31;
    const float* src = (gw < NN) ? (X + (size_t)gw * KK) : (Y + (size_t)(gw - NN) * KK);
    float s = 0.f;
    #pragma unroll
    for (int c = 0; c < KK; c += 32) {
        float a = src[c + lane];
        s = fmaf(a, a, s);
    }
    #pragma unroll
    for (int o = 16; o; o >>= 1) s += __shfl_xor_sync(0xffffffffu, s, o);
    if (lane == 0) {
        if (gw < NN) g_xs[gw] = s; else g_ys[gw - NN] = s;
    }
}

__global__ void init_kernel() {
    int i = blockIdx.x * 256 + threadIdx.x;
    if (i < NN) { g_u[i] = 0.f; g_v[i] = 0.f; }
}

// ---------------------------------------------------------------------------
// C2[i][j] = (|x_i|^2 + |y_j|^2 - 2 x_i . y_j) * SCALEF
// 128x128 block tile, 256 threads, 8x8 per thread, k-tile 8. fp32 FFMA.
__global__ __launch_bounds__(256) void gemm_kernel(const float* __restrict__ X,
                                                   const float* __restrict__ Y) {
    __shared__ float As[8][128];
    __shared__ float Bs[8][128];
    const int tid = threadIdx.x;
    const int bx = blockIdx.x;     // column tile (j)
    const int by = blockIdx.y;     // row tile (i)
    const int ar = tid >> 1;       // 0..127 : row within tile for global load
    const int ak = (tid & 1) * 4;  // 0 or 4 : k offset for float4 load
    const int tx = tid & 15;       // 0..15  : thread column
    const int ty = tid >> 4;       // 0..15  : thread row

    const float* xp = X + (size_t)(by * 128 + ar) * KK + ak;
    const float* yp = Y + (size_t)(bx * 128 + ar) * KK + ak;

    float acc[8][8];
    #pragma unroll
    for (int i = 0; i < 8; ++i)
        #pragma unroll
        for (int j = 0; j < 8; ++j) acc[i][j] = 0.f;

    for (int kt = 0; kt < KK; kt += 8) {
        float4 av = *(const float4*)(xp + kt);
        float4 bv = *(const float4*)(yp + kt);
        __syncthreads();
        As[ak + 0][ar] = av.x; As[ak + 1][ar] = av.y;
        As[ak + 2][ar] = av.z; As[ak + 3][ar] = av.w;
        Bs[ak + 0][ar] = bv.x; Bs[ak + 1][ar] = bv.y;
        Bs[ak + 2][ar] = bv.z; Bs[ak + 3][ar] = bv.w;
        __syncthreads();
        #pragma unroll
        for (int k = 0; k < 8; ++k) {
            float a[8], b[8];
            *(float4*)(a)     = *(const float4*)&As[k][ty * 8];
            *(float4*)(a + 4) = *(const float4*)&As[k][ty * 8 + 4];
            *(float4*)(b)     = *(const float4*)&Bs[k][tx * 8];
            *(float4*)(b + 4) = *(const float4*)&Bs[k][tx * 8 + 4];
            #pragma unroll
            for (int i = 0; i < 8; ++i)
                #pragma unroll
                for (int j = 0; j < 8; ++j)
                    acc[i][j] = fmaf(a[i], b[j], acc[i][j]);
        }
    }

    const int gi0 = by * 128 + ty * 8;
    const int gj0 = bx * 128 + tx * 8;
    float yv[8];
    #pragma unroll
    for (int j = 0; j < 8; ++j) yv[j] = g_ys[gj0 + j];
    #pragma unroll
    for (int i = 0; i < 8; ++i) {
        float xs = g_xs[gi0 + i];
        float4 o0, o1;
        o0.x = (xs + yv[0] - 2.f * acc[i][0]) * SCALEF;
        o0.y = (xs + yv[1] - 2.f * acc[i][1]) * SCALEF;
        o0.z = (xs + yv[2] - 2.f * acc[i][2]) * SCALEF;
        o0.w = (xs + yv[3] - 2.f * acc[i][3]) * SCALEF;
        o1.x = (xs + yv[4] - 2.f * acc[i][4]) * SCALEF;
        o1.y = (xs + yv[5] - 2.f * acc[i][5]) * SCALEF;
        o1.z = (xs + yv[6] - 2.f * acc[i][6]) * SCALEF;
        o1.w = (xs + yv[7] - 2.f * acc[i][7]) * SCALEF;
        float* dst = g_C2 + (size_t)(gi0 + i) * NN + gj0;
        *(float4*)(dst)     = o0;
        *(float4*)(dst + 4) = o1;
    }
}

// ---------------------------------------------------------------------------
// u pass: u2[i] = -( max_j t + log2 sum_j 2^(t - max) ),  t = v2[j] - C2[i][j]
// 512 blocks x 8 rows each, 256 threads. v2 slice cached in registers.
__global__ __launch_bounds__(256) void u_pass() {
    const int tid = threadIdx.x;
    float vv[16];
    #pragma unroll
    for (int k = 0; k < 16; ++k) vv[k] = g_v[tid + (k << 8)];

    __shared__ float red[8];
    const int row0 = blockIdx.x * 8;
    for (int rr = 0; rr < 8; ++rr) {
        const float* r = g_C2 + (size_t)(row0 + rr) * NN;
        float t[16];
        #pragma unroll
        for (int k = 0; k < 16; ++k) t[k] = vv[k] - r[tid + (k << 8)];
        float m = t[0];
        #pragma unroll
        for (int k = 1; k < 16; ++k) m = fmaxf(m, t[k]);
        #pragma unroll
        for (int o = 16; o; o >>= 1) m = fmaxf(m, __shfl_xor_sync(0xffffffffu, m, o));
        if ((tid & 31) == 0) red[tid >> 5] = m;
        __syncthreads();
        float bm = red[0];
        #pragma unroll
        for (int w = 1; w < 8; ++w) bm = fmaxf(bm, red[w]);
        __syncthreads();
        float s = 0.f;
        #pragma unroll
        for (int k = 0; k < 16; ++k) s += ex2f(t[k] - bm);
        #pragma unroll
        for (int o = 16; o; o >>= 1) s += __shfl_xor_sync(0xffffffffu, s, o);
        if ((tid & 31) == 0) red[tid >> 5] = s;
        __syncthreads();
        if (tid == 0) {
            float S = red[0];
            #pragma unroll
            for (int w = 1; w < 8; ++w) S += red[w];
            g_u[row0 + rr] = -(bm + lg2f(S));
        }
        __syncthreads();
    }
}

// ---------------------------------------------------------------------------
// v pass: v2[j] = -lse2_i( u2[i] - C2[i][j] )
// 256 blocks x 256 threads. Block handles 16 columns; thread (r = tid>>4,
// c = tid&15) walks rows i = r + 16q with chunked online max (1 EX2/elem + rare rescale).
__global__ __launch_bounds__(256) void v_pass() {
    const int tid = threadIdx.x;
    const int c = tid & 15;
    const int r = tid >> 4;
    const int j = blockIdx.x * 16 + c;

    __shared__ float su[NN];                 // 16 KB: whole u vector
    #pragma unroll
    for (int i = tid; i < NN; i += 256) su[i] = g_u[i];
    __syncthreads();

    const float* base = g_C2 + j;
    float m = NEG_BIG, s = 0.f;
    for (int q0 = 0; q0 < 256; q0 += 16) {
        float t[16];
        #pragma unroll
        for (int k = 0; k < 16; ++k) {
            int i = r + ((q0 + k) << 4);
            t[k] = su[i] - base[(size_t)i * NN];
        }
        float mc = t[0];
        #pragma unroll
        for (int k = 1; k < 16; ++k) mc = fmaxf(mc, t[k]);
        if (mc > m) { s *= ex2f(m - mc); m = mc; }
        #pragma unroll
        for (int k = 0; k < 16; ++k) s += ex2f(t[k] - m);
    }

    __shared__ float sm[16][17];
    __shared__ float ss[16][17];
    sm[r][c] = m; ss[r][c] = s;
    __syncthreads();
    if (tid < 16) {
        int cc = tid;
        float M = sm[0][cc];
        #pragma unroll
        for (int rr2 = 1; rr2 < 16; ++rr2) M = fmaxf(M, sm[rr2][cc]);
        float S = 0.f;
        #pragma unroll
        for (int rr2 = 0; rr2 < 16; ++rr2) S += ss[rr2][cc] * ex2f(sm[rr2][cc] - M);
        g_v[blockIdx.x * 16 + cc] = -(M + lg2f(S));
    }
}

// ---------------------------------------------------------------------------
// final: g_part[i] = sum_j 2^(u2[i] + v2[j] - C2[ij]) * C2[ij]
// 512 blocks x 8 rows, v2 in regs.
__global__ __launch_bounds__(256) void cost_pass() {
    const int tid = threadIdx.x;
    float vv[16];
    #pragma unroll
    for (int k = 0; k < 16; ++k) vv[k] = g_v[tid + (k << 8)];

    __shared__ float red[8];
    const int row0 = blockIdx.x * 8;
    for (int rr = 0; rr < 8; ++rr) {
        const int row = row0 + rr;
        const float u = g_u[row];
        const float* r = g_C2 + (size_t)row * NN;
        float s = 0.f;
        #pragma unroll
        for (int k = 0; k < 16; ++k) {
            float cc = r[tid + (k << 8)];
            s = fmaf(ex2f(u + vv[k] - cc), cc, s);
        }
        #pragma unroll
        for (int o = 16; o; o >>= 1) s += __shfl_xor_sync(0xffffffffu, s, o);
        if ((tid & 31) == 0) red[tid >> 5] = s;
        __syncthreads();
        if (tid == 0) {
            float S = red[0];
            #pragma unroll
            for (int w = 1; w < 8; ++w) S += red[w];
            g_part[row] = S;
        }
        __syncthreads();
    }
}

__global__ __launch_bounds__(256) void final_reduce(float* __restrict__ out) {
    const int tid = threadIdx.x;
    double s = 0.0;
    for (int i = tid; i < NN; i += 256) s += (double)g_part[i];
    __shared__ double red[256];
    red[tid] = s;
    __syncthreads();
    for (int o = 128; o; o >>= 1) {
        if (tid < o) red[tid] += red[tid + o];
        __syncthreads();
    }
    if (tid == 0) {
        // cost = sum(P*C)/N ; C = C2/SCALEF
        out[0] = (float)(red[0] / ((double)SCALEF * (double)NN));
    }
}

// ---------------------------------------------------------------------------
extern "C" void kernel_launch(void* const* d_in, const int* in_sizes, int n_in,
                              void* d_out, int out_size) {
    const float* x = (const float*)d_in[0];
    const float* y = (const float*)d_in[1];
    float* out = (float*)d_out;

    sqnorm_kernel<<<1024, 256>>>(x, y);
    init_kernel<<<16, 256>>>();
    gemm_kernel<<<dim3(32, 32), 256>>>(x, y);

    for (int it = 0; it < 100; ++it) {
        u_pass<<<512, 256>>>();
        v_pass<<<256, 256>>>();
    }

    cost_pass<<<512, 256>>>();
    final_reduce<<<1, 256>>>(out);
}